// round 12
// baseline (speedup 1.0000x reference)
#include <cuda_runtime.h>
#include <cuda_fp16.h>
#include <cstdint>

#define FEAT_IN   256
#define FEAT_OUT  64
#define MAX_N     100000
#define MAX_E     1600000
#define MAX_TOT   (MAX_E + MAX_N)
#define NEG_SLOPE 0.2f

// ---------------- scratch (device globals; no allocation allowed) ----------
__device__ __half g_hh[(size_t)MAX_N * FEAT_OUT];   // 12.8 MB fp16 h (gather-only)
__device__ float  g_asrc[MAX_N];
__device__ float  g_adst[MAX_N];
__device__ float  g_denom[MAX_N];
__device__ int    g_is64;

// ---------------- dtype detection: int64 vs int32 edge_index ---------------
// int64 indices in [0, N) with N < 2^31 have every odd 32-bit word zero.
__global__ void detect_kernel(const unsigned int* __restrict__ w, int nwords) {
    __shared__ unsigned int sacc[256];
    int npairs = nwords >> 1;
    int stride = (npairs + 1023) / 1024;
    if (stride < 1) stride = 1;
    unsigned int acc = 0;
    for (int i = threadIdx.x; i < 1024; i += blockDim.x) {
        long long pi = (long long)i * stride;
        if (pi < npairs) acc |= w[2 * pi + 1];
    }
    sacc[threadIdx.x] = acc;
    __syncthreads();
    for (int s = 128; s > 0; s >>= 1) {
        if (threadIdx.x < s) sacc[threadIdx.x] |= sacc[threadIdx.x + s];
        __syncthreads();
    }
    if (threadIdx.x == 0) g_is64 = (sacc[0] == 0u) ? 1 : 0;
}

// ---------------- zero out + denom (vectorized) -----------------------------
__global__ void zero_kernel(float4* __restrict__ out4, int n_out4, int N) {
    int i = blockIdx.x * blockDim.x + threadIdx.x;
    if (i < n_out4) out4[i] = make_float4(0.f, 0.f, 0.f, 0.f);
    if (i < N) g_denom[i] = 0.0f;
}

// ---------------- tf32 tensor-core GEMM + fused attention scores -----------
// h[N,64] = x[N,256] @ W[256,64];  a_src = h.att_src; a_dst = h.att_dst
// cp.async 2-stage double-buffered A (raw fp32, cvt->tf32 at fragment load);
// B register-staged transposed tf32 (conflict-free bank=(4g+q)%32).
#define BM 128
#define BK 32
#define BN 64
#define AS_STRIDE (BK + 4)

__device__ __forceinline__ uint32_t f2tf32(float f) {
    uint32_t u;
    asm("cvt.rna.tf32.f32 %0, %1;" : "=r"(u) : "f"(f));
    return u;
}

__device__ __forceinline__ uint32_t f2tf32u(uint32_t bits) {
    uint32_t u;
    asm("cvt.rna.tf32.f32 %0, %1;" : "=r"(u) : "f"(__uint_as_float(bits)));
    return u;
}

__global__ __launch_bounds__(256) void gemm_tf32_kernel(
    const float* __restrict__ x, const float* __restrict__ W,
    const float* __restrict__ att_src, const float* __restrict__ att_dst, int N) {
    __shared__ uint32_t As[2][BM][AS_STRIDE];   // raw fp32 bits
    __shared__ uint32_t Bs[2][BN][AS_STRIDE];   // transposed tf32: Bs[buf][n][k]
    __shared__ float sred[2][BM][2];

    const int t     = threadIdx.x;
    const int warp  = t >> 5, lane = t & 31;
    const int warpM = warp >> 1;
    const int warpN = warp & 1;
    const int g     = lane >> 2;
    const int q     = lane & 3;
    const int row0  = blockIdx.x * BM;

    const int bc  = t & 63;        // B staging: col
    const int br0 = t >> 6;        // B staging: k-row base (0..3)

    // A cp.async geometry: 4 chunks of 16B per thread per tile
    const int a_r[4]  = { (t + 0) >> 3, (t + 256) >> 3, (t + 512) >> 3, (t + 768) >> 3 };
    const int a_cq    = t & 7;

    float c[2][4][4];
#pragma unroll
    for (int mt = 0; mt < 2; mt++)
#pragma unroll
        for (int nt = 0; nt < 4; nt++)
#pragma unroll
            for (int i = 0; i < 4; i++) c[mt][nt][i] = 0.0f;

    // ---- issue cp.async for tile 0 ----
#pragma unroll
    for (int l = 0; l < 4; l++) {
        int r = a_r[l];
        int nrow = row0 + r;
        uint32_t dst = (uint32_t)__cvta_generic_to_shared(&As[0][r][a_cq * 4]);
        const float* src = &x[(size_t)nrow * FEAT_IN + a_cq * 4];
        int sz = (nrow < N) ? 16 : 0;
        asm volatile("cp.async.cg.shared.global [%0], [%1], 16, %2;\n"
                     :: "r"(dst), "l"(src), "r"(sz));
    }
    asm volatile("cp.async.commit_group;\n");

    // ---- B tile 0 into regs ----
    float rbv[8];
#pragma unroll
    for (int j = 0; j < 8; j++)
        rbv[j] = W[(size_t)(br0 + 4 * j) * FEAT_OUT + bc];

    const int NTILE = FEAT_IN / BK;   // 8
#pragma unroll 1
    for (int it = 0; it < NTILE; it++) {
        const int buf = it & 1;
        // wait for A(it); store B(it) to smem
        asm volatile("cp.async.wait_group 0;\n");
#pragma unroll
        for (int j = 0; j < 8; j++)
            Bs[buf][bc][br0 + 4 * j] = f2tf32(rbv[j]);
        __syncthreads();

        // prefetch tile it+1 (overlaps compute below)
        if (it + 1 < NTILE) {
            int kn = (it + 1) * BK;
#pragma unroll
            for (int l = 0; l < 4; l++) {
                int r = a_r[l];
                int nrow = row0 + r;
                uint32_t dst = (uint32_t)__cvta_generic_to_shared(&As[buf ^ 1][r][a_cq * 4]);
                const float* src = &x[(size_t)nrow * FEAT_IN + kn + a_cq * 4];
                int sz = (nrow < N) ? 16 : 0;
                asm volatile("cp.async.cg.shared.global [%0], [%1], 16, %2;\n"
                             :: "r"(dst), "l"(src), "r"(sz));
            }
            asm volatile("cp.async.commit_group;\n");
#pragma unroll
            for (int j = 0; j < 8; j++)
                rbv[j] = W[(size_t)(kn + br0 + 4 * j) * FEAT_OUT + bc];
        }

        // ---- compute on As[buf] (cvt at load), Bs[buf] ----
#pragma unroll
        for (int kk = 0; kk < BK; kk += 8) {
            uint32_t bf[4][2];
#pragma unroll
            for (int nt = 0; nt < 4; nt++) {
                int col = warpN * 32 + nt * 8 + g;
                bf[nt][0] = Bs[buf][col][kk + q];
                bf[nt][1] = Bs[buf][col][kk + q + 4];
            }
#pragma unroll
            for (int mt = 0; mt < 2; mt++) {
                int rbw = warpM * 32 + mt * 16;
                uint32_t a0 = f2tf32u(As[buf][rbw + g][kk + q]);
                uint32_t a1 = f2tf32u(As[buf][rbw + g + 8][kk + q]);
                uint32_t a2 = f2tf32u(As[buf][rbw + g][kk + q + 4]);
                uint32_t a3 = f2tf32u(As[buf][rbw + g + 8][kk + q + 4]);
#pragma unroll
                for (int nt = 0; nt < 4; nt++) {
                    asm volatile(
                        "mma.sync.aligned.m16n8k8.row.col.f32.tf32.tf32.f32 "
                        "{%0,%1,%2,%3}, {%4,%5,%6,%7}, {%8,%9}, {%0,%1,%2,%3};"
                        : "+f"(c[mt][nt][0]), "+f"(c[mt][nt][1]),
                          "+f"(c[mt][nt][2]), "+f"(c[mt][nt][3])
                        : "r"(a0), "r"(a1), "r"(a2), "r"(a3),
                          "r"(bf[nt][0]), "r"(bf[nt][1]));
                }
            }
        }
        // no trailing sync needed: next iter writes buf^1 only; the sync at
        // the top of the next iteration protects buf re-use two tiles out.
    }

    // ---- epilogue: store h (fp16), compute per-row att scores (fp32) ----
    float a_s[4][2], a_d[4][2];
#pragma unroll
    for (int nt = 0; nt < 4; nt++) {
        int col = warpN * 32 + nt * 8 + 2 * q;
        a_s[nt][0] = att_src[col];     a_s[nt][1] = att_src[col + 1];
        a_d[nt][0] = att_dst[col];     a_d[nt][1] = att_dst[col + 1];
    }
    float vs[2][2] = {{0, 0}, {0, 0}};
    float vd[2][2] = {{0, 0}, {0, 0}};
#pragma unroll
    for (int mt = 0; mt < 2; mt++) {
        int rbase = row0 + warpM * 32 + mt * 16 + g;
#pragma unroll
        for (int nt = 0; nt < 4; nt++) {
            int col = warpN * 32 + nt * 8 + 2 * q;
            float c0 = c[mt][nt][0], c1 = c[mt][nt][1];
            float c2 = c[mt][nt][2], c3 = c[mt][nt][3];
            vs[mt][0] += c0 * a_s[nt][0] + c1 * a_s[nt][1];
            vd[mt][0] += c0 * a_d[nt][0] + c1 * a_d[nt][1];
            vs[mt][1] += c2 * a_s[nt][0] + c3 * a_s[nt][1];
            vd[mt][1] += c2 * a_d[nt][0] + c3 * a_d[nt][1];
            if (rbase < N)
                ((__half2*)(g_hh + (size_t)rbase * FEAT_OUT))[col >> 1] =
                    __float22half2_rn(make_float2(c0, c1));
            if (rbase + 8 < N)
                ((__half2*)(g_hh + (size_t)(rbase + 8) * FEAT_OUT))[col >> 1] =
                    __float22half2_rn(make_float2(c2, c3));
        }
    }
#pragma unroll
    for (int mt = 0; mt < 2; mt++)
#pragma unroll
        for (int hh = 0; hh < 2; hh++) {
#pragma unroll
            for (int o = 1; o < 4; o <<= 1) {
                vs[mt][hh] += __shfl_xor_sync(0xffffffffu, vs[mt][hh], o);
                vd[mt][hh] += __shfl_xor_sync(0xffffffffu, vd[mt][hh], o);
            }
        }
    __syncthreads();   // sred reuse barrier (harmless; buffers idle now)
    if (q == 0) {
#pragma unroll
        for (int mt = 0; mt < 2; mt++) {
            int r = warpM * 32 + mt * 16 + g;
            sred[warpN][r][0] = vs[mt][0];
            sred[warpN][r][1] = vd[mt][0];
            sred[warpN][r + 8][0] = vs[mt][1];
            sred[warpN][r + 8][1] = vd[mt][1];
        }
    }
    __syncthreads();
    if (t < BM) {
        int nrow = row0 + t;
        if (nrow < N) {
            g_asrc[nrow] = sred[0][t][0] + sred[1][t][0];
            g_adst[nrow] = sred[0][t][1] + sred[1][t][1];
        }
    }
}

// ---------------- fused edge pass: w, denom, UNNORMALIZED aggregate --------
// out[d] += w * h[s] (h gathered fp16); denom[d] += w.  Division deferred to
// norm_kernel.  (Measured 85.9us — at the LTS RMW-op floor; do not touch.)
__global__ __launch_bounds__(256) void edge_kernel(const void* __restrict__ ei_raw,
                                                   float* __restrict__ out,
                                                   int E, int N) {
    __shared__ int   ss[256], sd[256];
    __shared__ float sw[256];
    const int tot  = E + N;
    const int base = blockIdx.x * 256;
    const int i    = base + threadIdx.x;

    if (i < tot) {
        int s, d;
        if (i < E) {
            if (g_is64) {
                const long long* p = (const long long*)ei_raw;
                s = (int)p[i];
                d = (int)p[(size_t)E + i];
            } else {
                const int* p = (const int*)ei_raw;
                s = p[i];
                d = p[E + i];
            }
        } else {
            s = d = i - E;   // self loop
        }
        float e = g_asrc[s] + g_adst[d];
        e = (e > 0.f) ? e : NEG_SLOPE * e;
        float w = __expf(e);
        ss[threadIdx.x] = s;
        sd[threadIdx.x] = d;
        sw[threadIdx.x] = w;
        atomicAdd(&g_denom[d], w);
    }
    __syncthreads();

    const int warp = threadIdx.x >> 5, lane = threadIdx.x & 31;
    const int half = lane >> 4, li = lane & 15;     // 2 edges per warp per iter
    const int nblk = min(256, tot - base);
#pragma unroll 8
    for (int it = 0; it < 16; it++) {
        int e = warp * 32 + it * 2 + half;
        if (e < nblk) {
            int s = ss[e], d = sd[e];
            float w = sw[e];
            uint2 hv = ((const uint2*)(g_hh + (size_t)s * FEAT_OUT))[li];
            __half2* ph = (__half2*)&hv;
            float2 f01 = __half22float2(ph[0]);
            float2 f23 = __half22float2(ph[1]);
            float* p = out + (size_t)d * FEAT_OUT + li * 4;
            asm volatile("red.global.add.v4.f32 [%0], {%1, %2, %3, %4};"
                         :: "l"(p), "f"(w * f01.x), "f"(w * f01.y),
                            "f"(w * f23.x), "f"(w * f23.y) : "memory");
        }
    }
}

// ---------------- divide by denom, add bias, row-wise L2 normalize ---------
__global__ void norm_kernel(float* __restrict__ out, const float* __restrict__ bias, int N) {
    int gw = (blockIdx.x * blockDim.x + threadIdx.x) >> 5;
    int lane = threadIdx.x & 31;
    if (gw >= N) return;
    float rd = __fdividef(1.0f, g_denom[gw]);
    float2 v = ((float2*)out)[(size_t)gw * 32 + lane];
    float2 b = ((const float2*)bias)[lane];
    v.x = v.x * rd + b.x;
    v.y = v.y * rd + b.y;
    float ss = v.x * v.x + v.y * v.y;
#pragma unroll
    for (int o = 16; o > 0; o >>= 1) ss += __shfl_xor_sync(0xffffffffu, ss, o);
    float inv = 1.0f / fmaxf(sqrtf(ss), 1e-12f);
    v.x *= inv; v.y *= inv;
    ((float2*)out)[(size_t)gw * 32 + lane] = v;
}

// ---------------- launch ----------------------------------------------------
extern "C" void kernel_launch(void* const* d_in, const int* in_sizes, int n_in,
                              void* d_out, int out_size) {
    const float* x       = (const float*)d_in[0];
    const void*  ei      = d_in[1];
    const float* W       = (const float*)d_in[2];
    const float* att_src = (const float*)d_in[3];
    const float* att_dst = (const float*)d_in[4];
    const float* bias    = (const float*)d_in[5];
    float*       out     = (float*)d_out;

    const int N   = in_sizes[0] / FEAT_IN;   // 100000
    const int E   = in_sizes[1] / 2;         // 1600000
    const int tot = E + N;
    const int n_out4 = (N * FEAT_OUT) / 4;

    detect_kernel<<<1, 256>>>((const unsigned int*)ei, 2 * E);
    zero_kernel<<<(n_out4 + 255) / 256, 256>>>((float4*)out, n_out4, N);
    gemm_tf32_kernel<<<(N + BM - 1) / BM, 256>>>(x, W, att_src, att_dst, N);
    edge_kernel<<<(tot + 255) / 256, 256>>>(ei, out, E, N);
    norm_kernel<<<(N + 7) / 8, 256>>>(out, bias, N);
}

// round 13
// speedup vs baseline: 1.4577x; 1.4577x over previous
#include <cuda_runtime.h>
#include <cuda_fp16.h>
#include <cstdint>

#define FEAT_IN   256
#define FEAT_OUT  64
#define MAX_N     100000
#define MAX_E     1600000
#define MAX_TOT   (MAX_E + MAX_N)
#define NEG_SLOPE 0.2f

// ---------------- scratch (device globals; no allocation allowed) ----------
__device__ __half g_hh[(size_t)MAX_N * FEAT_OUT];   // 12.8 MB fp16 h (gather-only)
__device__ float  g_asrc[MAX_N];
__device__ float  g_adst[MAX_N];
__device__ float  g_denom[MAX_N];
__device__ int    g_is64;

// ---------------- dtype detection: int64 vs int32 edge_index ---------------
// int64 indices in [0, N) with N < 2^31 have every odd 32-bit word zero.
__global__ void detect_kernel(const unsigned int* __restrict__ w, int nwords) {
    __shared__ unsigned int sacc[256];
    int npairs = nwords >> 1;
    int stride = (npairs + 1023) / 1024;
    if (stride < 1) stride = 1;
    unsigned int acc = 0;
    for (int i = threadIdx.x; i < 1024; i += blockDim.x) {
        long long pi = (long long)i * stride;
        if (pi < npairs) acc |= w[2 * pi + 1];
    }
    sacc[threadIdx.x] = acc;
    __syncthreads();
    for (int s = 128; s > 0; s >>= 1) {
        if (threadIdx.x < s) sacc[threadIdx.x] |= sacc[threadIdx.x + s];
        __syncthreads();
    }
    if (threadIdx.x == 0) g_is64 = (sacc[0] == 0u) ? 1 : 0;
}

// ---------------- zero out + denom (vectorized) -----------------------------
__global__ void zero_kernel(float4* __restrict__ out4, int n_out4, int N) {
    int i = blockIdx.x * blockDim.x + threadIdx.x;
    if (i < n_out4) out4[i] = make_float4(0.f, 0.f, 0.f, 0.f);
    if (i < N) g_denom[i] = 0.0f;
}

// ---------------- tf32 tensor-core GEMM + fused attention scores -----------
// h[N,64] = x[N,256] @ W[256,64];  a_src = h.att_src; a_dst = h.att_dst
// Register double-buffered; conflict-free smem fragment loads:
//   As stride 36 -> bank=(4g+q)%32 distinct; Bs transposed [n][k] stride 36.
// (This exact configuration measured ~43us in R10 — known-good.)
#define BM 128
#define BK 32
#define BN 64
#define AS_STRIDE (BK + 4)

__device__ __forceinline__ uint32_t f2tf32(float f) {
    uint32_t u;
    asm("cvt.rna.tf32.f32 %0, %1;" : "=r"(u) : "f"(f));
    return u;
}

__global__ __launch_bounds__(256) void gemm_tf32_kernel(
    const float* __restrict__ x, const float* __restrict__ W,
    const float* __restrict__ att_src, const float* __restrict__ att_dst, int N) {
    __shared__ uint32_t As[BM][AS_STRIDE];
    __shared__ uint32_t Bs[BN][AS_STRIDE];     // transposed: Bs[n][k]
    __shared__ float sred[2][BM][2];

    const int t     = threadIdx.x;
    const int warp  = t >> 5, lane = t & 31;
    const int warpM = warp >> 1;
    const int warpN = warp & 1;
    const int g     = lane >> 2;
    const int q     = lane & 3;
    const int row0  = blockIdx.x * BM;

    const int bc  = t & 63;        // B staging: col
    const int br0 = t >> 6;        // B staging: k-row base (0..3)

    float c[2][4][4];
#pragma unroll
    for (int mt = 0; mt < 2; mt++)
#pragma unroll
        for (int nt = 0; nt < 4; nt++)
#pragma unroll
            for (int i = 0; i < 4; i++) c[mt][nt][i] = 0.0f;

    float4 ra[4];
    float  rbv[8];
    // ---- prefetch tile 0 ----
#pragma unroll
    for (int l = 0; l < 4; l++) {
        int idx = t + l * 256;
        int r = idx >> 3, cq = idx & 7;
        int nrow = row0 + r;
        ra[l] = make_float4(0.f, 0.f, 0.f, 0.f);
        if (nrow < N) ra[l] = *(const float4*)&x[(size_t)nrow * FEAT_IN + cq * 4];
    }
#pragma unroll
    for (int j = 0; j < 8; j++)
        rbv[j] = W[(size_t)(br0 + 4 * j) * FEAT_OUT + bc];

    for (int k0 = 0; k0 < FEAT_IN; k0 += BK) {
        // ---- store staged regs to smem (cvt to tf32) ----
#pragma unroll
        for (int l = 0; l < 4; l++) {
            int idx = t + l * 256;
            int r = idx >> 3, cq = idx & 7;
            uint4 u = make_uint4(f2tf32(ra[l].x), f2tf32(ra[l].y),
                                 f2tf32(ra[l].z), f2tf32(ra[l].w));
            *(uint4*)&As[r][cq * 4] = u;
        }
#pragma unroll
        for (int j = 0; j < 8; j++)
            Bs[bc][br0 + 4 * j] = f2tf32(rbv[j]);
        __syncthreads();

        // ---- prefetch next tile (overlaps with compute) ----
        if (k0 + BK < FEAT_IN) {
            int kn = k0 + BK;
#pragma unroll
            for (int l = 0; l < 4; l++) {
                int idx = t + l * 256;
                int r = idx >> 3, cq = idx & 7;
                int nrow = row0 + r;
                ra[l] = make_float4(0.f, 0.f, 0.f, 0.f);
                if (nrow < N) ra[l] = *(const float4*)&x[(size_t)nrow * FEAT_IN + kn + cq * 4];
            }
#pragma unroll
            for (int j = 0; j < 8; j++)
                rbv[j] = W[(size_t)(kn + br0 + 4 * j) * FEAT_OUT + bc];
        }

        // ---- compute ----
#pragma unroll
        for (int kk = 0; kk < BK; kk += 8) {
            uint32_t bf[4][2];
#pragma unroll
            for (int nt = 0; nt < 4; nt++) {
                int col = warpN * 32 + nt * 8 + g;
                bf[nt][0] = Bs[col][kk + q];
                bf[nt][1] = Bs[col][kk + q + 4];
            }
#pragma unroll
            for (int mt = 0; mt < 2; mt++) {
                int rbw = warpM * 32 + mt * 16;
                uint32_t a0 = As[rbw + g][kk + q];
                uint32_t a1 = As[rbw + g + 8][kk + q];
                uint32_t a2 = As[rbw + g][kk + q + 4];
                uint32_t a3 = As[rbw + g + 8][kk + q + 4];
#pragma unroll
                for (int nt = 0; nt < 4; nt++) {
                    asm volatile(
                        "mma.sync.aligned.m16n8k8.row.col.f32.tf32.tf32.f32 "
                        "{%0,%1,%2,%3}, {%4,%5,%6,%7}, {%8,%9}, {%0,%1,%2,%3};"
                        : "+f"(c[mt][nt][0]), "+f"(c[mt][nt][1]),
                          "+f"(c[mt][nt][2]), "+f"(c[mt][nt][3])
                        : "r"(a0), "r"(a1), "r"(a2), "r"(a3),
                          "r"(bf[nt][0]), "r"(bf[nt][1]));
                }
            }
        }
        __syncthreads();
    }

    // ---- epilogue: store h (fp16), compute per-row att scores (fp32) ----
    float a_s[4][2], a_d[4][2];
#pragma unroll
    for (int nt = 0; nt < 4; nt++) {
        int col = warpN * 32 + nt * 8 + 2 * q;
        a_s[nt][0] = att_src[col];     a_s[nt][1] = att_src[col + 1];
        a_d[nt][0] = att_dst[col];     a_d[nt][1] = att_dst[col + 1];
    }
    float vs[2][2] = {{0, 0}, {0, 0}};
    float vd[2][2] = {{0, 0}, {0, 0}};
#pragma unroll
    for (int mt = 0; mt < 2; mt++) {
        int rbase = row0 + warpM * 32 + mt * 16 + g;
#pragma unroll
        for (int nt = 0; nt < 4; nt++) {
            int col = warpN * 32 + nt * 8 + 2 * q;
            float c0 = c[mt][nt][0], c1 = c[mt][nt][1];
            float c2 = c[mt][nt][2], c3 = c[mt][nt][3];
            vs[mt][0] += c0 * a_s[nt][0] + c1 * a_s[nt][1];
            vd[mt][0] += c0 * a_d[nt][0] + c1 * a_d[nt][1];
            vs[mt][1] += c2 * a_s[nt][0] + c3 * a_s[nt][1];
            vd[mt][1] += c2 * a_d[nt][0] + c3 * a_d[nt][1];
            if (rbase < N)
                ((__half2*)(g_hh + (size_t)rbase * FEAT_OUT))[col >> 1] =
                    __float22half2_rn(make_float2(c0, c1));
            if (rbase + 8 < N)
                ((__half2*)(g_hh + (size_t)(rbase + 8) * FEAT_OUT))[col >> 1] =
                    __float22half2_rn(make_float2(c2, c3));
        }
    }
#pragma unroll
    for (int mt = 0; mt < 2; mt++)
#pragma unroll
        for (int hh = 0; hh < 2; hh++) {
#pragma unroll
            for (int o = 1; o < 4; o <<= 1) {
                vs[mt][hh] += __shfl_xor_sync(0xffffffffu, vs[mt][hh], o);
                vd[mt][hh] += __shfl_xor_sync(0xffffffffu, vd[mt][hh], o);
            }
        }
    if (q == 0) {
#pragma unroll
        for (int mt = 0; mt < 2; mt++) {
            int r = warpM * 32 + mt * 16 + g;
            sred[warpN][r][0] = vs[mt][0];
            sred[warpN][r][1] = vd[mt][0];
            sred[warpN][r + 8][0] = vs[mt][1];
            sred[warpN][r + 8][1] = vd[mt][1];
        }
    }
    __syncthreads();
    if (t < BM) {
        int nrow = row0 + t;
        if (nrow < N) {
            g_asrc[nrow] = sred[0][t][0] + sred[1][t][0];
            g_adst[nrow] = sred[0][t][1] + sred[1][t][1];
        }
    }
}

// ---------------- fused edge pass: w, denom, UNNORMALIZED aggregate --------
// out[d] += w * h[s] (h gathered fp16); denom[d] += w.  Division deferred to
// norm_kernel.  (Measured 85.9us at good clocks — LTS RMW-op floor.)
__global__ __launch_bounds__(256) void edge_kernel(const void* __restrict__ ei_raw,
                                                   float* __restrict__ out,
                                                   int E, int N) {
    __shared__ int   ss[256], sd[256];
    __shared__ float sw[256];
    const int tot  = E + N;
    const int base = blockIdx.x * 256;
    const int i    = base + threadIdx.x;

    if (i < tot) {
        int s, d;
        if (i < E) {
            if (g_is64) {
                const long long* p = (const long long*)ei_raw;
                s = (int)p[i];
                d = (int)p[(size_t)E + i];
            } else {
                const int* p = (const int*)ei_raw;
                s = p[i];
                d = p[E + i];
            }
        } else {
            s = d = i - E;   // self loop
        }
        float e = g_asrc[s] + g_adst[d];
        e = (e > 0.f) ? e : NEG_SLOPE * e;
        float w = __expf(e);
        ss[threadIdx.x] = s;
        sd[threadIdx.x] = d;
        sw[threadIdx.x] = w;
        atomicAdd(&g_denom[d], w);
    }
    __syncthreads();

    const int warp = threadIdx.x >> 5, lane = threadIdx.x & 31;
    const int half = lane >> 4, li = lane & 15;     // 2 edges per warp per iter
    const int nblk = min(256, tot - base);
#pragma unroll 8
    for (int it = 0; it < 16; it++) {
        int e = warp * 32 + it * 2 + half;
        if (e < nblk) {
            int s = ss[e], d = sd[e];
            float w = sw[e];
            uint2 hv = ((const uint2*)(g_hh + (size_t)s * FEAT_OUT))[li];
            __half2* ph = (__half2*)&hv;
            float2 f01 = __half22float2(ph[0]);
            float2 f23 = __half22float2(ph[1]);
            float* p = out + (size_t)d * FEAT_OUT + li * 4;
            asm volatile("red.global.add.v4.f32 [%0], {%1, %2, %3, %4};"
                         :: "l"(p), "f"(w * f01.x), "f"(w * f01.y),
                            "f"(w * f23.x), "f"(w * f23.y) : "memory");
        }
    }
}

// ---------------- divide by denom, add bias, row-wise L2 normalize ---------
__global__ void norm_kernel(float* __restrict__ out, const float* __restrict__ bias, int N) {
    int gw = (blockIdx.x * blockDim.x + threadIdx.x) >> 5;
    int lane = threadIdx.x & 31;
    if (gw >= N) return;
    float rd = __fdividef(1.0f, g_denom[gw]);
    float2 v = ((float2*)out)[(size_t)gw * 32 + lane];
    float2 b = ((const float2*)bias)[lane];
    v.x = v.x * rd + b.x;
    v.y = v.y * rd + b.y;
    float ss = v.x * v.x + v.y * v.y;
#pragma unroll
    for (int o = 16; o > 0; o >>= 1) ss += __shfl_xor_sync(0xffffffffu, ss, o);
    float inv = 1.0f / fmaxf(sqrtf(ss), 1e-12f);
    v.x *= inv; v.y *= inv;
    ((float2*)out)[(size_t)gw * 32 + lane] = v;
}

// ---------------- launch ----------------------------------------------------
extern "C" void kernel_launch(void* const* d_in, const int* in_sizes, int n_in,
                              void* d_out, int out_size) {
    const float* x       = (const float*)d_in[0];
    const void*  ei      = d_in[1];
    const float* W       = (const float*)d_in[2];
    const float* att_src = (const float*)d_in[3];
    const float* att_dst = (const float*)d_in[4];
    const float* bias    = (const float*)d_in[5];
    float*       out     = (float*)d_out;

    const int N   = in_sizes[0] / FEAT_IN;   // 100000
    const int E   = in_sizes[1] / 2;         // 1600000
    const int tot = E + N;
    const int n_out4 = (N * FEAT_OUT) / 4;

    detect_kernel<<<1, 256>>>((const unsigned int*)ei, 2 * E);
    zero_kernel<<<(n_out4 + 255) / 256, 256>>>((float4*)out, n_out4, N);
    gemm_tf32_kernel<<<(N + BM - 1) / BM, 256>>>(x, W, att_src, att_dst, N);
    edge_kernel<<<(tot + 255) / 256, 256>>>(ei, out, E, N);
    norm_kernel<<<(N + 7) / 8, 256>>>(out, bias, N);
}

// round 14
// speedup vs baseline: 1.6091x; 1.1038x over previous
#include <cuda_runtime.h>
#include <cuda_fp16.h>
#include <cstdint>

#define FEAT_IN   256
#define FEAT_OUT  64
#define MAX_N     100000
#define MAX_E     1600000
#define MAX_TOT   (MAX_E + MAX_N)
#define NEG_SLOPE 0.2f

// ---------------- scratch (device globals; no allocation allowed) ----------
__device__ __half g_hh[(size_t)MAX_N * FEAT_OUT];   // 12.8 MB fp16 h (gather-only)
__device__ float  g_asrc[MAX_N];
__device__ float  g_adst[MAX_N];
__device__ float  g_denom[MAX_N];
__device__ int    g_is64;

// ---------------- zero out/denom + fused int64-vs-int32 detection ----------
// Block 0 additionally detects edge_index dtype: int64 indices in [0, N)
// with N < 2^31 have every odd 32-bit word zero.
__global__ void zero_detect_kernel(float4* __restrict__ out4, int n_out4, int N,
                                   const unsigned int* __restrict__ w, int nwords) {
    int i = blockIdx.x * blockDim.x + threadIdx.x;
    if (i < n_out4) out4[i] = make_float4(0.f, 0.f, 0.f, 0.f);
    if (i < N) g_denom[i] = 0.0f;
    if (blockIdx.x == 0) {
        __shared__ unsigned int sacc[256];
        int npairs = nwords >> 1;
        int stride = (npairs + 1023) / 1024;
        if (stride < 1) stride = 1;
        unsigned int acc = 0;
        for (int k = threadIdx.x; k < 1024; k += blockDim.x) {
            long long pi = (long long)k * stride;
            if (pi < npairs) acc |= w[2 * pi + 1];
        }
        sacc[threadIdx.x] = acc;
        __syncthreads();
        for (int s = 128; s > 0; s >>= 1) {
            if (threadIdx.x < s) sacc[threadIdx.x] |= sacc[threadIdx.x + s];
            __syncthreads();
        }
        if (threadIdx.x == 0) g_is64 = (sacc[0] == 0u) ? 1 : 0;
    }
}

// ---------------- fp16 tensor-core GEMM + fused attention scores -----------
// h[N,64] = x[N,256] @ W[256,64];  a_src = h.att_src; a_dst = h.att_dst
// mma.sync.m16n8k16.f16 with fp32 accumulation — same 10-bit mantissa as
// tf32 but half the MMA instruction count. Register double-buffered.
// Smem packed half2, row stride 20 words -> fragment bank=(20g+q)%32: all 32
// lanes distinct (conflict-free, same property as the measured tf32 layout).
#define BM 128
#define BK 32
#define BN 64
#define KP  (BK / 2)          // 16 half2 k-pairs per row per tile
#define ST2 (KP + 4)          // 20: padded stride in uint32 words

__device__ __forceinline__ uint32_t pack_h2(float lo, float hi) {
    __half2 h = __floats2half2_rn(lo, hi);
    return *(uint32_t*)&h;
}

__global__ __launch_bounds__(256) void gemm_f16_kernel(
    const float* __restrict__ x, const float* __restrict__ W,
    const float* __restrict__ att_src, const float* __restrict__ att_dst, int N) {
    __shared__ uint32_t As[BM][ST2];   // half2-packed A: As[row][kpair]
    __shared__ uint32_t Bs[BN][ST2];   // transposed half2 B: Bs[col][kpair]
    __shared__ float sred[2][BM][2];

    const int t     = threadIdx.x;
    const int warp  = t >> 5, lane = t & 31;
    const int warpM = warp >> 1;
    const int warpN = warp & 1;
    const int g     = lane >> 2;
    const int q     = lane & 3;
    const int row0  = blockIdx.x * BM;

    const int bcB = t & 63;        // B staging: col (0..63)
    const int kp0 = t >> 6;        // B staging: kpair base (0..3)

    float c[2][4][4];
#pragma unroll
    for (int mt = 0; mt < 2; mt++)
#pragma unroll
        for (int nt = 0; nt < 4; nt++)
#pragma unroll
            for (int i = 0; i < 4; i++) c[mt][nt][i] = 0.0f;

    float4 ra[4];
    float2 rbf[4];
    // ---- prefetch tile 0 ----
#pragma unroll
    for (int l = 0; l < 4; l++) {
        int idx = t + l * 256;
        int r = idx >> 3, cq = idx & 7;
        int nrow = row0 + r;
        ra[l] = make_float4(0.f, 0.f, 0.f, 0.f);
        if (nrow < N) ra[l] = *(const float4*)&x[(size_t)nrow * FEAT_IN + cq * 4];
    }
#pragma unroll
    for (int j = 0; j < 4; j++) {
        int kp = kp0 + 4 * j;
        rbf[j].x = W[(size_t)(2 * kp) * FEAT_OUT + bcB];
        rbf[j].y = W[(size_t)(2 * kp + 1) * FEAT_OUT + bcB];
    }

    for (int k0 = 0; k0 < FEAT_IN; k0 += BK) {
        // ---- store staged regs to smem (pack to half2) ----
#pragma unroll
        for (int l = 0; l < 4; l++) {
            int idx = t + l * 256;
            int r = idx >> 3, cq = idx & 7;   // kpair offset = 2*cq
            uint2 u = make_uint2(pack_h2(ra[l].x, ra[l].y),
                                 pack_h2(ra[l].z, ra[l].w));
            *(uint2*)&As[r][cq * 2] = u;      // word index 20r+2cq: 8B aligned
        }
#pragma unroll
        for (int j = 0; j < 4; j++)
            Bs[bcB][kp0 + 4 * j] = pack_h2(rbf[j].x, rbf[j].y);
        __syncthreads();

        // ---- prefetch next tile (overlaps with compute) ----
        if (k0 + BK < FEAT_IN) {
            int kn = k0 + BK;
#pragma unroll
            for (int l = 0; l < 4; l++) {
                int idx = t + l * 256;
                int r = idx >> 3, cq = idx & 7;
                int nrow = row0 + r;
                ra[l] = make_float4(0.f, 0.f, 0.f, 0.f);
                if (nrow < N) ra[l] = *(const float4*)&x[(size_t)nrow * FEAT_IN + kn + cq * 4];
            }
#pragma unroll
            for (int j = 0; j < 4; j++) {
                int kp = kp0 + 4 * j;
                rbf[j].x = W[(size_t)(kn + 2 * kp) * FEAT_OUT + bcB];
                rbf[j].y = W[(size_t)(kn + 2 * kp + 1) * FEAT_OUT + bcB];
            }
        }

        // ---- compute: 2 k16 steps per 32-k tile ----
#pragma unroll
        for (int ko = 0; ko < 2; ko++) {
            const int kb = ko * 8;            // kpair base of this k16 step
            uint32_t bf[4][2];
#pragma unroll
            for (int nt = 0; nt < 4; nt++) {
                int col = warpN * 32 + nt * 8 + g;
                bf[nt][0] = Bs[col][kb + q];
                bf[nt][1] = Bs[col][kb + q + 4];
            }
#pragma unroll
            for (int mt = 0; mt < 2; mt++) {
                int rbw = warpM * 32 + mt * 16;
                uint32_t a0 = As[rbw + g][kb + q];
                uint32_t a1 = As[rbw + g + 8][kb + q];
                uint32_t a2 = As[rbw + g][kb + q + 4];
                uint32_t a3 = As[rbw + g + 8][kb + q + 4];
#pragma unroll
                for (int nt = 0; nt < 4; nt++) {
                    asm volatile(
                        "mma.sync.aligned.m16n8k16.row.col.f32.f16.f16.f32 "
                        "{%0,%1,%2,%3}, {%4,%5,%6,%7}, {%8,%9}, {%0,%1,%2,%3};"
                        : "+f"(c[mt][nt][0]), "+f"(c[mt][nt][1]),
                          "+f"(c[mt][nt][2]), "+f"(c[mt][nt][3])
                        : "r"(a0), "r"(a1), "r"(a2), "r"(a3),
                          "r"(bf[nt][0]), "r"(bf[nt][1]));
                }
            }
        }
        __syncthreads();
    }

    // ---- epilogue: store h (fp16), compute per-row att scores (fp32) ----
    float a_s[4][2], a_d[4][2];
#pragma unroll
    for (int nt = 0; nt < 4; nt++) {
        int col = warpN * 32 + nt * 8 + 2 * q;
        a_s[nt][0] = att_src[col];     a_s[nt][1] = att_src[col + 1];
        a_d[nt][0] = att_dst[col];     a_d[nt][1] = att_dst[col + 1];
    }
    float vs[2][2] = {{0, 0}, {0, 0}};
    float vd[2][2] = {{0, 0}, {0, 0}};
#pragma unroll
    for (int mt = 0; mt < 2; mt++) {
        int rbase = row0 + warpM * 32 + mt * 16 + g;
#pragma unroll
        for (int nt = 0; nt < 4; nt++) {
            int col = warpN * 32 + nt * 8 + 2 * q;
            float c0 = c[mt][nt][0], c1 = c[mt][nt][1];
            float c2 = c[mt][nt][2], c3 = c[mt][nt][3];
            vs[mt][0] += c0 * a_s[nt][0] + c1 * a_s[nt][1];
            vd[mt][0] += c0 * a_d[nt][0] + c1 * a_d[nt][1];
            vs[mt][1] += c2 * a_s[nt][0] + c3 * a_s[nt][1];
            vd[mt][1] += c2 * a_d[nt][0] + c3 * a_d[nt][1];
            if (rbase < N)
                ((__half2*)(g_hh + (size_t)rbase * FEAT_OUT))[col >> 1] =
                    __float22half2_rn(make_float2(c0, c1));
            if (rbase + 8 < N)
                ((__half2*)(g_hh + (size_t)(rbase + 8) * FEAT_OUT))[col >> 1] =
                    __float22half2_rn(make_float2(c2, c3));
        }
    }
#pragma unroll
    for (int mt = 0; mt < 2; mt++)
#pragma unroll
        for (int hh = 0; hh < 2; hh++) {
#pragma unroll
            for (int o = 1; o < 4; o <<= 1) {
                vs[mt][hh] += __shfl_xor_sync(0xffffffffu, vs[mt][hh], o);
                vd[mt][hh] += __shfl_xor_sync(0xffffffffu, vd[mt][hh], o);
            }
        }
    if (q == 0) {
#pragma unroll
        for (int mt = 0; mt < 2; mt++) {
            int r = warpM * 32 + mt * 16 + g;
            sred[warpN][r][0] = vs[mt][0];
            sred[warpN][r][1] = vd[mt][0];
            sred[warpN][r + 8][0] = vs[mt][1];
            sred[warpN][r + 8][1] = vd[mt][1];
        }
    }
    __syncthreads();
    if (t < BM) {
        int nrow = row0 + t;
        if (nrow < N) {
            g_asrc[nrow] = sred[0][t][0] + sred[1][t][0];
            g_adst[nrow] = sred[0][t][1] + sred[1][t][1];
        }
    }
}

// ---------------- fused edge pass: w, denom, UNNORMALIZED aggregate --------
// out[d] += w * h[s] (h gathered fp16); denom[d] += w.  Division deferred to
// norm_kernel.  (Measured 85.9-89.2us — LTS RMW-op floor; do not touch.)
__global__ __launch_bounds__(256) void edge_kernel(const void* __restrict__ ei_raw,
                                                   float* __restrict__ out,
                                                   int E, int N) {
    __shared__ int   ss[256], sd[256];
    __shared__ float sw[256];
    const int tot  = E + N;
    const int base = blockIdx.x * 256;
    const int i    = base + threadIdx.x;

    if (i < tot) {
        int s, d;
        if (i < E) {
            if (g_is64) {
                const long long* p = (const long long*)ei_raw;
                s = (int)p[i];
                d = (int)p[(size_t)E + i];
            } else {
                const int* p = (const int*)ei_raw;
                s = p[i];
                d = p[E + i];
            }
        } else {
            s = d = i - E;   // self loop
        }
        float e = g_asrc[s] + g_adst[d];
        e = (e > 0.f) ? e : NEG_SLOPE * e;
        float w = __expf(e);
        ss[threadIdx.x] = s;
        sd[threadIdx.x] = d;
        sw[threadIdx.x] = w;
        atomicAdd(&g_denom[d], w);
    }
    __syncthreads();

    const int warp = threadIdx.x >> 5, lane = threadIdx.x & 31;
    const int half = lane >> 4, li = lane & 15;     // 2 edges per warp per iter
    const int nblk = min(256, tot - base);
#pragma unroll 8
    for (int it = 0; it < 16; it++) {
        int e = warp * 32 + it * 2 + half;
        if (e < nblk) {
            int s = ss[e], d = sd[e];
            float w = sw[e];
            uint2 hv = ((const uint2*)(g_hh + (size_t)s * FEAT_OUT))[li];
            __half2* ph = (__half2*)&hv;
            float2 f01 = __half22float2(ph[0]);
            float2 f23 = __half22float2(ph[1]);
            float* p = out + (size_t)d * FEAT_OUT + li * 4;
            asm volatile("red.global.add.v4.f32 [%0], {%1, %2, %3, %4};"
                         :: "l"(p), "f"(w * f01.x), "f"(w * f01.y),
                            "f"(w * f23.x), "f"(w * f23.y) : "memory");
        }
    }
}

// ---------------- divide by denom, add bias, row-wise L2 normalize ---------
__global__ void norm_kernel(float* __restrict__ out, const float* __restrict__ bias, int N) {
    int gw = (blockIdx.x * blockDim.x + threadIdx.x) >> 5;
    int lane = threadIdx.x & 31;
    if (gw >= N) return;
    float rd = __fdividef(1.0f, g_denom[gw]);
    float2 v = ((float2*)out)[(size_t)gw * 32 + lane];
    float2 b = ((const float2*)bias)[lane];
    v.x = v.x * rd + b.x;
    v.y = v.y * rd + b.y;
    float ss = v.x * v.x + v.y * v.y;
#pragma unroll
    for (int o = 16; o > 0; o >>= 1) ss += __shfl_xor_sync(0xffffffffu, ss, o);
    float inv = 1.0f / fmaxf(sqrtf(ss), 1e-12f);
    v.x *= inv; v.y *= inv;
    ((float2*)out)[(size_t)gw * 32 + lane] = v;
}

// ---------------- launch ----------------------------------------------------
extern "C" void kernel_launch(void* const* d_in, const int* in_sizes, int n_in,
                              void* d_out, int out_size) {
    const float* x       = (const float*)d_in[0];
    const void*  ei      = d_in[1];
    const float* W       = (const float*)d_in[2];
    const float* att_src = (const float*)d_in[3];
    const float* att_dst = (const float*)d_in[4];
    const float* bias    = (const float*)d_in[5];
    float*       out     = (float*)d_out;

    const int N   = in_sizes[0] / FEAT_IN;   // 100000
    const int E   = in_sizes[1] / 2;         // 1600000
    const int tot = E + N;
    const int n_out4 = (N * FEAT_OUT) / 4;

    zero_detect_kernel<<<(n_out4 + 255) / 256, 256>>>((float4*)out, n_out4, N,
                                                      (const unsigned int*)ei, 2 * E);
    gemm_f16_kernel<<<(N + BM - 1) / BM, 256>>>(x, W, att_src, att_dst, N);
    edge_kernel<<<(tot + 255) / 256, 256>>>(ei, out, E, N);
    norm_kernel<<<(N + 7) / 8, 256>>>(out, bias, N);
}

// round 16
// speedup vs baseline: 1.6596x; 1.0314x over previous
#include <cuda_runtime.h>
#include <cuda_fp16.h>
#include <cstdint>

#define FEAT_IN   256
#define FEAT_OUT  64
#define MAX_N     100000
#define MAX_E     1600000
#define MAX_TOT   (MAX_E + MAX_N)
#define NEG_SLOPE 0.2f

// ---------------- scratch (device globals; no allocation allowed) ----------
__device__ __half g_hh[(size_t)MAX_N * FEAT_OUT];   // 12.8 MB fp16 h (gather-only)
__device__ float  g_asrc[MAX_N];
__device__ float  g_adst[MAX_N];
__device__ float  g_denom[MAX_N];
__device__ int    g_is64;

// ---------------- zero out/denom + fused int64-vs-int32 detection ----------
// Block 0 additionally detects edge_index dtype: int64 indices in [0, N)
// with N < 2^31 have every odd 32-bit word zero.
__global__ void zero_detect_kernel(float4* __restrict__ out4, int n_out4, int N,
                                   const unsigned int* __restrict__ w, int nwords) {
    int i = blockIdx.x * blockDim.x + threadIdx.x;
    if (i < n_out4) out4[i] = make_float4(0.f, 0.f, 0.f, 0.f);
    if (i < N) g_denom[i] = 0.0f;
    if (blockIdx.x == 0) {
        __shared__ unsigned int sacc[256];
        int npairs = nwords >> 1;
        int stride = (npairs + 1023) / 1024;
        if (stride < 1) stride = 1;
        unsigned int acc = 0;
        for (int k = threadIdx.x; k < 1024; k += blockDim.x) {
            long long pi = (long long)k * stride;
            if (pi < npairs) acc |= w[2 * pi + 1];
        }
        sacc[threadIdx.x] = acc;
        __syncthreads();
        for (int s = 128; s > 0; s >>= 1) {
            if (threadIdx.x < s) sacc[threadIdx.x] |= sacc[threadIdx.x + s];
            __syncthreads();
        }
        if (threadIdx.x == 0) g_is64 = (sacc[0] == 0u) ? 1 : 0;
    }
}

// ---------------- fp16 tensor-core GEMM + fused attention scores -----------
// h[N,64] = x[N,256] @ W[256,64];  a_src = h.att_src; a_dst = h.att_dst
// mma.sync.m16n8k16.f16 fp32-accum; register double-buffered; conflict-free
// half2 smem (stride 20 words -> fragment bank=(20g+q)%32 all distinct).
// (Measured ~29us in R14 — known-good.)
#define BM 128
#define BK 32
#define BN 64
#define KP  (BK / 2)          // 16 half2 k-pairs per row per tile
#define ST2 (KP + 4)          // 20: padded stride in uint32 words

__device__ __forceinline__ uint32_t pack_h2(float lo, float hi) {
    __half2 h = __floats2half2_rn(lo, hi);
    return *(uint32_t*)&h;
}

__global__ __launch_bounds__(256) void gemm_f16_kernel(
    const float* __restrict__ x, const float* __restrict__ W,
    const float* __restrict__ att_src, const float* __restrict__ att_dst, int N) {
    __shared__ uint32_t As[BM][ST2];   // half2-packed A: As[row][kpair]
    __shared__ uint32_t Bs[BN][ST2];   // transposed half2 B: Bs[col][kpair]
    __shared__ float sred[2][BM][2];

    const int t     = threadIdx.x;
    const int warp  = t >> 5, lane = t & 31;
    const int warpM = warp >> 1;
    const int warpN = warp & 1;
    const int g     = lane >> 2;
    const int q     = lane & 3;
    const int row0  = blockIdx.x * BM;

    const int bcB = t & 63;        // B staging: col (0..63)
    const int kp0 = t >> 6;        // B staging: kpair base (0..3)

    float c[2][4][4];
#pragma unroll
    for (int mt = 0; mt < 2; mt++)
#pragma unroll
        for (int nt = 0; nt < 4; nt++)
#pragma unroll
            for (int i = 0; i < 4; i++) c[mt][nt][i] = 0.0f;

    float4 ra[4];
    float2 rbf[4];
    // ---- prefetch tile 0 ----
#pragma unroll
    for (int l = 0; l < 4; l++) {
        int idx = t + l * 256;
        int r = idx >> 3, cq = idx & 7;
        int nrow = row0 + r;
        ra[l] = make_float4(0.f, 0.f, 0.f, 0.f);
        if (nrow < N) ra[l] = *(const float4*)&x[(size_t)nrow * FEAT_IN + cq * 4];
    }
#pragma unroll
    for (int j = 0; j < 4; j++) {
        int kp = kp0 + 4 * j;
        rbf[j].x = W[(size_t)(2 * kp) * FEAT_OUT + bcB];
        rbf[j].y = W[(size_t)(2 * kp + 1) * FEAT_OUT + bcB];
    }

    for (int k0 = 0; k0 < FEAT_IN; k0 += BK) {
        // ---- store staged regs to smem (pack to half2) ----
#pragma unroll
        for (int l = 0; l < 4; l++) {
            int idx = t + l * 256;
            int r = idx >> 3, cq = idx & 7;   // kpair offset = 2*cq
            uint2 u = make_uint2(pack_h2(ra[l].x, ra[l].y),
                                 pack_h2(ra[l].z, ra[l].w));
            *(uint2*)&As[r][cq * 2] = u;      // word index 20r+2cq: 8B aligned
        }
#pragma unroll
        for (int j = 0; j < 4; j++)
            Bs[bcB][kp0 + 4 * j] = pack_h2(rbf[j].x, rbf[j].y);
        __syncthreads();

        // ---- prefetch next tile (overlaps with compute) ----
        if (k0 + BK < FEAT_IN) {
            int kn = k0 + BK;
#pragma unroll
            for (int l = 0; l < 4; l++) {
                int idx = t + l * 256;
                int r = idx >> 3, cq = idx & 7;
                int nrow = row0 + r;
                ra[l] = make_float4(0.f, 0.f, 0.f, 0.f);
                if (nrow < N) ra[l] = *(const float4*)&x[(size_t)nrow * FEAT_IN + kn + cq * 4];
            }
#pragma unroll
            for (int j = 0; j < 4; j++) {
                int kp = kp0 + 4 * j;
                rbf[j].x = W[(size_t)(kn + 2 * kp) * FEAT_OUT + bcB];
                rbf[j].y = W[(size_t)(kn + 2 * kp + 1) * FEAT_OUT + bcB];
            }
        }

        // ---- compute: 2 k16 steps per 32-k tile ----
#pragma unroll
        for (int ko = 0; ko < 2; ko++) {
            const int kb = ko * 8;            // kpair base of this k16 step
            uint32_t bf[4][2];
#pragma unroll
            for (int nt = 0; nt < 4; nt++) {
                int col = warpN * 32 + nt * 8 + g;
                bf[nt][0] = Bs[col][kb + q];
                bf[nt][1] = Bs[col][kb + q + 4];
            }
#pragma unroll
            for (int mt = 0; mt < 2; mt++) {
                int rbw = warpM * 32 + mt * 16;
                uint32_t a0 = As[rbw + g][kb + q];
                uint32_t a1 = As[rbw + g + 8][kb + q];
                uint32_t a2 = As[rbw + g][kb + q + 4];
                uint32_t a3 = As[rbw + g + 8][kb + q + 4];
#pragma unroll
                for (int nt = 0; nt < 4; nt++) {
                    asm volatile(
                        "mma.sync.aligned.m16n8k16.row.col.f32.f16.f16.f32 "
                        "{%0,%1,%2,%3}, {%4,%5,%6,%7}, {%8,%9}, {%0,%1,%2,%3};"
                        : "+f"(c[mt][nt][0]), "+f"(c[mt][nt][1]),
                          "+f"(c[mt][nt][2]), "+f"(c[mt][nt][3])
                        : "r"(a0), "r"(a1), "r"(a2), "r"(a3),
                          "r"(bf[nt][0]), "r"(bf[nt][1]));
                }
            }
        }
        __syncthreads();
    }

    // ---- epilogue: store h (fp16), compute per-row att scores (fp32) ----
    float a_s[4][2], a_d[4][2];
#pragma unroll
    for (int nt = 0; nt < 4; nt++) {
        int col = warpN * 32 + nt * 8 + 2 * q;
        a_s[nt][0] = att_src[col];     a_s[nt][1] = att_src[col + 1];
        a_d[nt][0] = att_dst[col];     a_d[nt][1] = att_dst[col + 1];
    }
    float vs[2][2] = {{0, 0}, {0, 0}};
    float vd[2][2] = {{0, 0}, {0, 0}};
#pragma unroll
    for (int mt = 0; mt < 2; mt++) {
        int rbase = row0 + warpM * 32 + mt * 16 + g;
#pragma unroll
        for (int nt = 0; nt < 4; nt++) {
            int col = warpN * 32 + nt * 8 + 2 * q;
            float c0 = c[mt][nt][0], c1 = c[mt][nt][1];
            float c2 = c[mt][nt][2], c3 = c[mt][nt][3];
            vs[mt][0] += c0 * a_s[nt][0] + c1 * a_s[nt][1];
            vd[mt][0] += c0 * a_d[nt][0] + c1 * a_d[nt][1];
            vs[mt][1] += c2 * a_s[nt][0] + c3 * a_s[nt][1];
            vd[mt][1] += c2 * a_d[nt][0] + c3 * a_d[nt][1];
            if (rbase < N)
                ((__half2*)(g_hh + (size_t)rbase * FEAT_OUT))[col >> 1] =
                    __float22half2_rn(make_float2(c0, c1));
            if (rbase + 8 < N)
                ((__half2*)(g_hh + (size_t)(rbase + 8) * FEAT_OUT))[col >> 1] =
                    __float22half2_rn(make_float2(c2, c3));
        }
    }
#pragma unroll
    for (int mt = 0; mt < 2; mt++)
#pragma unroll
        for (int hh = 0; hh < 2; hh++) {
#pragma unroll
            for (int o = 1; o < 4; o <<= 1) {
                vs[mt][hh] += __shfl_xor_sync(0xffffffffu, vs[mt][hh], o);
                vd[mt][hh] += __shfl_xor_sync(0xffffffffu, vd[mt][hh], o);
            }
        }
    if (q == 0) {
#pragma unroll
        for (int mt = 0; mt < 2; mt++) {
            int r = warpM * 32 + mt * 16 + g;
            sred[warpN][r][0] = vs[mt][0];
            sred[warpN][r][1] = vd[mt][0];
            sred[warpN][r + 8][0] = vs[mt][1];
            sred[warpN][r + 8][1] = vd[mt][1];
        }
    }
    __syncthreads();
    if (t < BM) {
        int nrow = row0 + t;
        if (nrow < N) {
            g_asrc[nrow] = sred[0][t][0] + sred[1][t][0];
            g_adst[nrow] = sred[0][t][1] + sred[1][t][1];
        }
    }
}

// ---------------- fused edge pass: w, denom, UNNORMALIZED aggregate --------
// out[d] += w * h[s] (h gathered fp16); denom[d] += w.  Division deferred to
// norm_kernel.  (Measured 85.9-89.2us — LTS RMW-op floor; do not touch.)
__global__ __launch_bounds__(256) void edge_kernel(const void* __restrict__ ei_raw,
                                                   float* __restrict__ out,
                                                   int E, int N) {
    __shared__ int   ss[256], sd[256];
    __shared__ float sw[256];
    const int tot  = E + N;
    const int base = blockIdx.x * 256;
    const int i    = base + threadIdx.x;

    if (i < tot) {
        int s, d;
        if (i < E) {
            if (g_is64) {
                const long long* p = (const long long*)ei_raw;
                s = (int)p[i];
                d = (int)p[(size_t)E + i];
            } else {
                const int* p = (const int*)ei_raw;
                s = p[i];
                d = p[E + i];
            }
        } else {
            s = d = i - E;   // self loop
        }
        float e = g_asrc[s] + g_adst[d];
        e = (e > 0.f) ? e : NEG_SLOPE * e;
        float w = __expf(e);
        ss[threadIdx.x] = s;
        sd[threadIdx.x] = d;
        sw[threadIdx.x] = w;
        atomicAdd(&g_denom[d], w);
    }
    __syncthreads();

    const int warp = threadIdx.x >> 5, lane = threadIdx.x & 31;
    const int half = lane >> 4, li = lane & 15;     // 2 edges per warp per iter
    const int nblk = min(256, tot - base);
#pragma unroll 8
    for (int it = 0; it < 16; it++) {
        int e = warp * 32 + it * 2 + half;
        if (e < nblk) {
            int s = ss[e], d = sd[e];
            float w = sw[e];
            uint2 hv = ((const uint2*)(g_hh + (size_t)s * FEAT_OUT))[li];
            __half2* ph = (__half2*)&hv;
            float2 f01 = __half22float2(ph[0]);
            float2 f23 = __half22float2(ph[1]);
            float* p = out + (size_t)d * FEAT_OUT + li * 4;
            asm volatile("red.global.add.v4.f32 [%0], {%1, %2, %3, %4};"
                         :: "l"(p), "f"(w * f01.x), "f"(w * f01.y),
                            "f"(w * f23.x), "f"(w * f23.y) : "memory");
        }
    }
}

// ---------------- divide by denom, add bias, row-wise L2 normalize ---------
// 16 lanes per row (float4 each), 2 rows per warp: 128-bit accesses, 4-step
// half-warp reduction, 2 independent rows in flight per warp.
__global__ __launch_bounds__(256) void norm_kernel(float* __restrict__ out,
                                                   const float* __restrict__ bias, int N) {
    int warp_id = (blockIdx.x * blockDim.x + threadIdx.x) >> 5;
    int lane = threadIdx.x & 31;
    int li   = lane & 15;            // lane within row
    int row  = warp_id * 2 + (lane >> 4);
    if (row >= N) return;
    float rd = __fdividef(1.0f, g_denom[row]);
    float4 v = ((const float4*)out)[(size_t)row * 16 + li];
    float4 b = ((const float4*)bias)[li];
    v.x = v.x * rd + b.x;
    v.y = v.y * rd + b.y;
    v.z = v.z * rd + b.z;
    v.w = v.w * rd + b.w;
    float ss = v.x * v.x + v.y * v.y + v.z * v.z + v.w * v.w;
#pragma unroll
    for (int o = 8; o > 0; o >>= 1) ss += __shfl_xor_sync(0xffffffffu, ss, o);
    float inv = 1.0f / fmaxf(sqrtf(ss), 1e-12f);
    v.x *= inv; v.y *= inv; v.z *= inv; v.w *= inv;
    ((float4*)out)[(size_t)row * 16 + li] = v;
}

// ---------------- launch ----------------------------------------------------
extern "C" void kernel_launch(void* const* d_in, const int* in_sizes, int n_in,
                              void* d_out, int out_size) {
    const float* x       = (const float*)d_in[0];
    const void*  ei      = d_in[1];
    const float* W       = (const float*)d_in[2];
    const float* att_src = (const float*)d_in[3];
    const float* att_dst = (const float*)d_in[4];
    const float* bias    = (const float*)d_in[5];
    float*       out     = (float*)d_out;

    const int N   = in_sizes[0] / FEAT_IN;   // 100000
    const int E   = in_sizes[1] / 2;         // 1600000
    const int tot = E + N;
    const int n_out4 = (N * FEAT_OUT) / 4;

    zero_detect_kernel<<<(n_out4 + 255) / 256, 256>>>((float4*)out, n_out4, N,
                                                      (const unsigned int*)ei, 2 * E);
    gemm_f16_kernel<<<(N + BM - 1) / BM, 256>>>(x, W, att_src, att_dst, N);
    edge_kernel<<<(tot + 255) / 256, 256>>>(ei, out, E, N);
    // 2 rows per warp, 16 warps' worth of rows per 256-thread block
    norm_kernel<<<(N + 15) / 16, 256>>>(out, bias, N);
}

// round 17
// speedup vs baseline: 1.6899x; 1.0183x over previous
#include <cuda_runtime.h>
#include <cuda_fp16.h>
#include <cstdint>

#define FEAT_IN   256
#define FEAT_OUT  64
#define MAX_N     100000
#define MAX_E     1600000
#define NEG_SLOPE 0.2f

// ---------------- scratch (device globals; no allocation allowed) ----------
__device__ __half g_hh[(size_t)MAX_N * FEAT_OUT];   // 12.8 MB fp16 h (gather-only)
__device__ float  g_asrc[MAX_N];
__device__ float  g_adst[MAX_N];
__device__ float  g_denom[MAX_N];
__device__ int    g_is64;

// ---------------- zero out/denom + fused int64-vs-int32 detection ----------
__global__ void zero_detect_kernel(float4* __restrict__ out4, int n_out4, int N,
                                   const unsigned int* __restrict__ w, int nwords) {
    int i = blockIdx.x * blockDim.x + threadIdx.x;
    if (i < n_out4) out4[i] = make_float4(0.f, 0.f, 0.f, 0.f);
    if (i < N) g_denom[i] = 0.0f;
    if (blockIdx.x == 0) {
        __shared__ unsigned int sacc[256];
        int npairs = nwords >> 1;
        int stride = (npairs + 1023) / 1024;
        if (stride < 1) stride = 1;
        unsigned int acc = 0;
        for (int k = threadIdx.x; k < 1024; k += blockDim.x) {
            long long pi = (long long)k * stride;
            if (pi < npairs) acc |= w[2 * pi + 1];
        }
        sacc[threadIdx.x] = acc;
        __syncthreads();
        for (int s = 128; s > 0; s >>= 1) {
            if (threadIdx.x < s) sacc[threadIdx.x] |= sacc[threadIdx.x + s];
            __syncthreads();
        }
        if (threadIdx.x == 0) g_is64 = (sacc[0] == 0u) ? 1 : 0;
    }
}

// ---------------- fp16 tensor-core GEMM + fused attention scores -----------
// h[N,64] = x[N,256] @ W[256,64];  a_src = h.att_src; a_dst = h.att_dst
// Double-buffered smem, ONE sync per k-tile. Conflict-free half2 layout
// (stride 20 words -> fragment bank=(20g+q)%32 all distinct).
#define BM 128
#define BK 32
#define BN 64
#define KP  (BK / 2)          // 16 half2 k-pairs per row per tile
#define ST2 (KP + 4)          // 20: padded stride in uint32 words
#define NTILE (FEAT_IN / BK)  // 8

__device__ __forceinline__ uint32_t pack_h2(float lo, float hi) {
    __half2 h = __floats2half2_rn(lo, hi);
    return *(uint32_t*)&h;
}

__global__ __launch_bounds__(256) void gemm_f16_kernel(
    const float* __restrict__ x, const float* __restrict__ W,
    const float* __restrict__ att_src, const float* __restrict__ att_dst, int N) {
    __shared__ uint32_t As[2][BM][ST2];   // half2-packed A
    __shared__ uint32_t Bs[2][BN][ST2];   // transposed half2 B
    __shared__ float sred[2][BM][2];

    const int t     = threadIdx.x;
    const int warp  = t >> 5, lane = t & 31;
    const int warpM = warp >> 1;
    const int warpN = warp & 1;
    const int g     = lane >> 2;
    const int q     = lane & 3;
    const int row0  = blockIdx.x * BM;

    const int bcB = t & 63;        // B staging: col (0..63)
    const int kp0 = t >> 6;        // B staging: kpair base (0..3)

    float c[2][4][4];
#pragma unroll
    for (int mt = 0; mt < 2; mt++)
#pragma unroll
        for (int nt = 0; nt < 4; nt++)
#pragma unroll
            for (int i = 0; i < 4; i++) c[mt][nt][i] = 0.0f;

    float4 ra[4];
    float2 rbf[4];
    // ---- prefetch tile 0 into regs ----
#pragma unroll
    for (int l = 0; l < 4; l++) {
        int idx = t + l * 256;
        int r = idx >> 3, cq = idx & 7;
        int nrow = row0 + r;
        ra[l] = make_float4(0.f, 0.f, 0.f, 0.f);
        if (nrow < N) ra[l] = *(const float4*)&x[(size_t)nrow * FEAT_IN + cq * 4];
    }
#pragma unroll
    for (int j = 0; j < 4; j++) {
        int kp = kp0 + 4 * j;
        rbf[j].x = W[(size_t)(2 * kp) * FEAT_OUT + bcB];
        rbf[j].y = W[(size_t)(2 * kp + 1) * FEAT_OUT + bcB];
    }
    // ---- stage tile 0 -> smem[0] ----
#pragma unroll
    for (int l = 0; l < 4; l++) {
        int idx = t + l * 256;
        int r = idx >> 3, cq = idx & 7;
        uint2 u = make_uint2(pack_h2(ra[l].x, ra[l].y), pack_h2(ra[l].z, ra[l].w));
        *(uint2*)&As[0][r][cq * 2] = u;
    }
#pragma unroll
    for (int j = 0; j < 4; j++)
        Bs[0][bcB][kp0 + 4 * j] = pack_h2(rbf[j].x, rbf[j].y);
    __syncthreads();

#pragma unroll 1
    for (int it = 0; it < NTILE; it++) {
        const int buf = it & 1;
        // ---- prefetch tile it+1 into regs (lands during compute) ----
        if (it + 1 < NTILE) {
            int kn = (it + 1) * BK;
#pragma unroll
            for (int l = 0; l < 4; l++) {
                int idx = t + l * 256;
                int r = idx >> 3, cq = idx & 7;
                int nrow = row0 + r;
                ra[l] = make_float4(0.f, 0.f, 0.f, 0.f);
                if (nrow < N) ra[l] = *(const float4*)&x[(size_t)nrow * FEAT_IN + kn + cq * 4];
            }
#pragma unroll
            for (int j = 0; j < 4; j++) {
                int kp = kp0 + 4 * j;
                rbf[j].x = W[(size_t)(kn + 2 * kp) * FEAT_OUT + bcB];
                rbf[j].y = W[(size_t)(kn + 2 * kp + 1) * FEAT_OUT + bcB];
            }
        }

        // ---- compute on smem[buf]: 2 k16 steps ----
#pragma unroll
        for (int ko = 0; ko < 2; ko++) {
            const int kb = ko * 8;
            uint32_t bf[4][2];
#pragma unroll
            for (int nt = 0; nt < 4; nt++) {
                int col = warpN * 32 + nt * 8 + g;
                bf[nt][0] = Bs[buf][col][kb + q];
                bf[nt][1] = Bs[buf][col][kb + q + 4];
            }
#pragma unroll
            for (int mt = 0; mt < 2; mt++) {
                int rbw = warpM * 32 + mt * 16;
                uint32_t a0 = As[buf][rbw + g][kb + q];
                uint32_t a1 = As[buf][rbw + g + 8][kb + q];
                uint32_t a2 = As[buf][rbw + g][kb + q + 4];
                uint32_t a3 = As[buf][rbw + g + 8][kb + q + 4];
#pragma unroll
                for (int nt = 0; nt < 4; nt++) {
                    asm volatile(
                        "mma.sync.aligned.m16n8k16.row.col.f32.f16.f16.f32 "
                        "{%0,%1,%2,%3}, {%4,%5,%6,%7}, {%8,%9}, {%0,%1,%2,%3};"
                        : "+f"(c[mt][nt][0]), "+f"(c[mt][nt][1]),
                          "+f"(c[mt][nt][2]), "+f"(c[mt][nt][3])
                        : "r"(a0), "r"(a1), "r"(a2), "r"(a3),
                          "r"(bf[nt][0]), "r"(bf[nt][1]));
                }
            }
        }

        // ---- stage tile it+1 -> smem[buf^1] (safe: last read of buf^1 was
        // in iter it-1, whose ending sync all warps have passed) ----
        if (it + 1 < NTILE) {
#pragma unroll
            for (int l = 0; l < 4; l++) {
                int idx = t + l * 256;
                int r = idx >> 3, cq = idx & 7;
                uint2 u = make_uint2(pack_h2(ra[l].x, ra[l].y), pack_h2(ra[l].z, ra[l].w));
                *(uint2*)&As[buf ^ 1][r][cq * 2] = u;
            }
#pragma unroll
            for (int j = 0; j < 4; j++)
                Bs[buf ^ 1][bcB][kp0 + 4 * j] = pack_h2(rbf[j].x, rbf[j].y);
        }
        __syncthreads();
    }

    // ---- epilogue: store h (fp16), compute per-row att scores (fp32) ----
    float a_s[4][2], a_d[4][2];
#pragma unroll
    for (int nt = 0; nt < 4; nt++) {
        int col = warpN * 32 + nt * 8 + 2 * q;
        a_s[nt][0] = att_src[col];     a_s[nt][1] = att_src[col + 1];
        a_d[nt][0] = att_dst[col];     a_d[nt][1] = att_dst[col + 1];
    }
    float vs[2][2] = {{0, 0}, {0, 0}};
    float vd[2][2] = {{0, 0}, {0, 0}};
#pragma unroll
    for (int mt = 0; mt < 2; mt++) {
        int rbase = row0 + warpM * 32 + mt * 16 + g;
#pragma unroll
        for (int nt = 0; nt < 4; nt++) {
            int col = warpN * 32 + nt * 8 + 2 * q;
            float c0 = c[mt][nt][0], c1 = c[mt][nt][1];
            float c2 = c[mt][nt][2], c3 = c[mt][nt][3];
            vs[mt][0] += c0 * a_s[nt][0] + c1 * a_s[nt][1];
            vd[mt][0] += c0 * a_d[nt][0] + c1 * a_d[nt][1];
            vs[mt][1] += c2 * a_s[nt][0] + c3 * a_s[nt][1];
            vd[mt][1] += c2 * a_d[nt][0] + c3 * a_d[nt][1];
            if (rbase < N)
                ((__half2*)(g_hh + (size_t)rbase * FEAT_OUT))[col >> 1] =
                    __float22half2_rn(make_float2(c0, c1));
            if (rbase + 8 < N)
                ((__half2*)(g_hh + (size_t)(rbase + 8) * FEAT_OUT))[col >> 1] =
                    __float22half2_rn(make_float2(c2, c3));
        }
    }
#pragma unroll
    for (int mt = 0; mt < 2; mt++)
#pragma unroll
        for (int hh = 0; hh < 2; hh++) {
#pragma unroll
            for (int o = 1; o < 4; o <<= 1) {
                vs[mt][hh] += __shfl_xor_sync(0xffffffffu, vs[mt][hh], o);
                vd[mt][hh] += __shfl_xor_sync(0xffffffffu, vd[mt][hh], o);
            }
        }
    if (q == 0) {
#pragma unroll
        for (int mt = 0; mt < 2; mt++) {
            int r = warpM * 32 + mt * 16 + g;
            sred[warpN][r][0] = vs[mt][0];
            sred[warpN][r][1] = vd[mt][0];
            sred[warpN][r + 8][0] = vs[mt][1];
            sred[warpN][r + 8][1] = vd[mt][1];
        }
    }
    __syncthreads();
    if (t < BM) {
        int nrow = row0 + t;
        if (nrow < N) {
            g_asrc[nrow] = sred[0][t][0] + sred[1][t][0];
            g_adst[nrow] = sred[0][t][1] + sred[1][t][1];
        }
    }
}

// ---------------- fused edge pass over REAL edges only ---------------------
// out[d] += w * h[s] (fp16 gather); denom[d] += w.  Self-loops are folded
// into norm_kernel (row-local there). Division deferred to norm_kernel.
__global__ __launch_bounds__(256) void edge_kernel(const void* __restrict__ ei_raw,
                                                   float* __restrict__ out, int E) {
    __shared__ int   ss[256], sd[256];
    __shared__ float sw[256];
    const int base = blockIdx.x * 256;
    const int i    = base + threadIdx.x;

    if (i < E) {
        int s, d;
        if (g_is64) {
            const long long* p = (const long long*)ei_raw;
            s = (int)p[i];
            d = (int)p[(size_t)E + i];
        } else {
            const int* p = (const int*)ei_raw;
            s = p[i];
            d = p[E + i];
        }
        float e = g_asrc[s] + g_adst[d];
        e = (e > 0.f) ? e : NEG_SLOPE * e;
        float w = __expf(e);
        ss[threadIdx.x] = s;
        sd[threadIdx.x] = d;
        sw[threadIdx.x] = w;
        atomicAdd(&g_denom[d], w);
    }
    __syncthreads();

    const int warp = threadIdx.x >> 5, lane = threadIdx.x & 31;
    const int half = lane >> 4, li = lane & 15;     // 2 edges per warp per iter
    const int nblk = min(256, E - base);
#pragma unroll 8
    for (int it = 0; it < 16; it++) {
        int e = warp * 32 + it * 2 + half;
        if (e < nblk) {
            int s = ss[e], d = sd[e];
            float w = sw[e];
            uint2 hv = ((const uint2*)(g_hh + (size_t)s * FEAT_OUT))[li];
            __half2* ph = (__half2*)&hv;
            float2 f01 = __half22float2(ph[0]);
            float2 f23 = __half22float2(ph[1]);
            float* p = out + (size_t)d * FEAT_OUT + li * 4;
            asm volatile("red.global.add.v4.f32 [%0], {%1, %2, %3, %4};"
                         :: "l"(p), "f"(w * f01.x), "f"(w * f01.y),
                            "f"(w * f23.x), "f"(w * f23.y) : "memory");
        }
    }
}

// ---------------- self-loop + divide + bias + row-wise L2 normalize --------
// 16 lanes per row (float4 each), 2 rows per warp. Adds the self-loop term
// w_self*h[row] and w_self to the denominator before normalizing.
__global__ __launch_bounds__(256) void norm_kernel(float* __restrict__ out,
                                                   const float* __restrict__ bias, int N) {
    int warp_id = (blockIdx.x * blockDim.x + threadIdx.x) >> 5;
    int lane = threadIdx.x & 31;
    int li   = lane & 15;            // lane within row
    int row  = warp_id * 2 + (lane >> 4);
    if (row >= N) return;
    // self-loop weight (row-local)
    float e = g_asrc[row] + g_adst[row];
    e = (e > 0.f) ? e : NEG_SLOPE * e;
    float w = __expf(e);
    float rd = __fdividef(1.0f, g_denom[row] + w);
    // self-loop h contribution (fp16, same path as edge gathers)
    uint2 hv = ((const uint2*)(g_hh + (size_t)row * FEAT_OUT))[li];
    __half2* ph = (__half2*)&hv;
    float2 f01 = __half22float2(ph[0]);
    float2 f23 = __half22float2(ph[1]);
    float4 v = ((const float4*)out)[(size_t)row * 16 + li];
    float4 b = ((const float4*)bias)[li];
    v.x = (v.x + w * f01.x) * rd + b.x;
    v.y = (v.y + w * f01.y) * rd + b.y;
    v.z = (v.z + w * f23.x) * rd + b.z;
    v.w = (v.w + w * f23.y) * rd + b.w;
    float ss = v.x * v.x + v.y * v.y + v.z * v.z + v.w * v.w;
#pragma unroll
    for (int o = 8; o > 0; o >>= 1) ss += __shfl_xor_sync(0xffffffffu, ss, o);
    float inv = 1.0f / fmaxf(sqrtf(ss), 1e-12f);
    v.x *= inv; v.y *= inv; v.z *= inv; v.w *= inv;
    ((float4*)out)[(size_t)row * 16 + li] = v;
}

// ---------------- launch ----------------------------------------------------
extern "C" void kernel_launch(void* const* d_in, const int* in_sizes, int n_in,
                              void* d_out, int out_size) {
    const float* x       = (const float*)d_in[0];
    const void*  ei      = d_in[1];
    const float* W       = (const float*)d_in[2];
    const float* att_src = (const float*)d_in[3];
    const float* att_dst = (const float*)d_in[4];
    const float* bias    = (const float*)d_in[5];
    float*       out     = (float*)d_out;

    const int N = in_sizes[0] / FEAT_IN;   // 100000
    const int E = in_sizes[1] / 2;         // 1600000
    const int n_out4 = (N * FEAT_OUT) / 4;

    zero_detect_kernel<<<(n_out4 + 255) / 256, 256>>>((float4*)out, n_out4, N,
                                                      (const unsigned int*)ei, 2 * E);
    gemm_f16_kernel<<<(N + BM - 1) / BM, 256>>>(x, W, att_src, att_dst, N);
    edge_kernel<<<(E + 255) / 256, 256>>>(ei, out, E);
    norm_kernel<<<(N + 15) / 16, 256>>>(out, bias, N);
}